// round 3
// baseline (speedup 1.0000x reference)
#include <cuda_runtime.h>
#include <cstddef>

#define NN 64          // sequence length
#define G  16          // batches per block
#define TB 256         // threads per block (16 per batch)

// shared layout (floats)
#define SA2_OFF 0                       // [32 entries][64 n]            = 2048
#define SB3_OFF 2048                    // [16 chunks][64 n][4 jk]       = 4096
#define SX_OFF  (SB3_OFF + 4096)        // G * 65 float2                 = 2080
#define SHP_OFF (SX_OFF + 2080)         // G * 16 halfprods * 17 (pad)   = 4352
#define SQ_OFF  (SHP_OFF + 4352)        // G * 8 * 4                     = 512
#define ST_OFF  (SQ_OFF + 512)          // G * 8 * 4                     = 512
#define SVL_OFF (ST_OFF + 512)          // G * 64 float4                 = 4096
#define SVR_OFF (SVL_OFF + 4096)        // G * 64 float4                 = 4096
#define SMEM_FLOATS (SVR_OFF + 4096)    // 21792 floats = 87168 B

// robust NaN->0 (bit test, immune to fast-math folding)
__device__ __forceinline__ float nan0(float h) {
    unsigned u = __float_as_uint(h);
    return ((u & 0x7fffffffu) > 0x7f800000u) ? 0.0f : h;
}

__global__ __launch_bounds__(TB, 2)
void tdvp_kernel(const float* __restrict__ xg, const float* __restrict__ Ag,
                 const float* __restrict__ Bg, const float* __restrict__ sg,
                 float* __restrict__ yg)
{
    extern __shared__ float sm[];
    float*  sA2 = sm + SA2_OFF;                // A[entry][n], entry = 2*(l*4+r)+i
    float*  sB3 = sm + SB3_OFF;                // B[(c*64+n)*4 + jk], c = i*4+l
    float2* sx  = (float2*)(sm + SX_OFF);      // [g*65 + n]
    float*  sHP = sm + SHP_OFF;                // [g*272 + h*17 + e]
    float*  sQ  = sm + SQ_OFF;                 // [g*32 + s*4]
    float*  sT  = sm + ST_OFF;                 // [g*32 + s*4]
    float4* svL = (float4*)(sm + SVL_OFF);     // [g*64 + n]
    float4* svR = (float4*)(sm + SVR_OFF);     // [g*64 + n]

    const int tid = threadIdx.x;
    const int b0  = blockIdx.x * G;

    // ---- stage inputs (smem-layout-friendly indexing; A/B are tiny & L2-hot) ----
    for (int i = tid; i < NN * 32; i += TB) {          // sA2[e*64+n] = A[n*32+e]
        int n = i & 63, e = i >> 6;
        sA2[i] = Ag[n * 32 + e];
    }
    for (int i = tid; i < NN * 64; i += TB) {          // sB3[(c*64+n)*4+jk] = B[n*64+c*4+jk]
        int jk = i & 3, n = (i >> 2) & 63, c = i >> 8;
        sB3[i] = Bg[n * 64 + c * 4 + jk];
    }
    const float2* xv = (const float2*)xg;
    for (int idx = tid; idx < G * NN; idx += TB) {
        float2 v = xv[(size_t)b0 * NN + idx];
        float inv = rsqrtf(v.x * v.x + v.y * v.y);
        v.x *= inv; v.y *= inv;
        sx[(idx >> 6) * 65 + (idx & 63)] = v;
    }
    __syncthreads();

    const int g    = tid >> 4;        // batch in block
    const int t_in = tid & 15;

    // M-build: M[e] = A[n,e,0]*x + A[n,e,1]*y  (e = l*4+r, row-major)
    auto buildM = [&](int n, float* Md) {
        float2 xn = sx[g * 65 + n];
        #pragma unroll
        for (int e = 0; e < 16; ++e)
            Md[e] = fmaf(sA2[(2 * e) * 64 + n], xn.x, sA2[(2 * e + 1) * 64 + n] * xn.y);
    };

    // ---- stage 1: half-segment products HP_h = M[4h]*M[4h+1]*M[4h+2]*M[4h+3] ----
    {
        const int h = t_in;
        float P[16], Mk[16];
        buildM(4 * h, P);
        #pragma unroll
        for (int k = 1; k < 4; ++k) {
            buildM(4 * h + k, Mk);
            float Pn[16];
            #pragma unroll
            for (int i = 0; i < 4; ++i)
                #pragma unroll
                for (int c = 0; c < 4; ++c)
                    Pn[i * 4 + c] = P[i*4+0]*Mk[0*4+c] + P[i*4+1]*Mk[1*4+c]
                                  + P[i*4+2]*Mk[2*4+c] + P[i*4+3]*Mk[3*4+c];
            #pragma unroll
            for (int e = 0; e < 16; ++e) P[e] = Pn[e];
        }
        float* hp = sHP + g * 272 + h * 17;
        #pragma unroll
        for (int e = 0; e < 16; ++e) hp[e] = P[e];
    }
    __syncthreads();

    // ---- stage 2: boundary vectors over half-products (2 threads per batch) ----
    if (t_in == 0) {
        // q_h = e0^T HP_0 ... HP_{h-1}; store q_{2s} for s=0..7
        float v[4] = {1.f, 0.f, 0.f, 0.f};
        sQ[g * 32 + 0] = 1.f; sQ[g * 32 + 1] = 0.f; sQ[g * 32 + 2] = 0.f; sQ[g * 32 + 3] = 0.f;
        #pragma unroll 1
        for (int h = 0; h < 15; ++h) {
            const float* hp = sHP + g * 272 + h * 17;
            float t0 = v[0]*hp[0]  + v[1]*hp[4]  + v[2]*hp[8]  + v[3]*hp[12];
            float t1 = v[0]*hp[1]  + v[1]*hp[5]  + v[2]*hp[9]  + v[3]*hp[13];
            float t2 = v[0]*hp[2]  + v[1]*hp[6]  + v[2]*hp[10] + v[3]*hp[14];
            float t3 = v[0]*hp[3]  + v[1]*hp[7]  + v[2]*hp[11] + v[3]*hp[15];
            v[0] = t0; v[1] = t1; v[2] = t2; v[3] = t3;
            if ((h & 1) == 1) {                    // after HP_h, v = q_{h+1}, h+1 even
                int s = (h + 1) >> 1;
                float* q = sQ + g * 32 + s * 4;
                q[0] = v[0]; q[1] = v[1]; q[2] = v[2]; q[3] = v[3];
            }
        }
    } else if (t_in == 8) {
        // T_h = HP_h ... HP_15 e0; store T_{2s+2} at slot s (T_16 = e0 at s=7)
        float r[4] = {1.f, 0.f, 0.f, 0.f};
        sT[g * 32 + 7 * 4 + 0] = 1.f; sT[g * 32 + 7 * 4 + 1] = 0.f;
        sT[g * 32 + 7 * 4 + 2] = 0.f; sT[g * 32 + 7 * 4 + 3] = 0.f;
        #pragma unroll 1
        for (int h = 15; h >= 2; --h) {
            const float* hp = sHP + g * 272 + h * 17;
            float t0 = hp[0]*r[0]  + hp[1]*r[1]  + hp[2]*r[2]  + hp[3]*r[3];
            float t1 = hp[4]*r[0]  + hp[5]*r[1]  + hp[6]*r[2]  + hp[7]*r[3];
            float t2 = hp[8]*r[0]  + hp[9]*r[1]  + hp[10]*r[2] + hp[11]*r[3];
            float t3 = hp[12]*r[0] + hp[13]*r[1] + hp[14]*r[2] + hp[15]*r[3];
            r[0] = t0; r[1] = t1; r[2] = t2; r[3] = t3;
            if ((h & 1) == 0) {                    // r = T_h, h even >= 2
                int s = (h - 2) >> 1;
                float* tp = sT + g * 32 + s * 4;
                tp[0] = r[0]; tp[1] = r[1]; tp[2] = r[2]; tp[3] = r[3];
            }
        }
    }
    __syncthreads();

    // ---- stage 3: expand 8 positions per thread ----
    {
        const int dir = t_in >> 3;
        const int s   = t_in & 7;
        float Mk[16];
        if (dir == 0) {
            // vL[n] = e0^T M[0..n-1]; start from q_{2s}
            const float* q = sQ + g * 32 + s * 4;
            float v0 = q[0], v1 = q[1], v2 = q[2], v3 = q[3];
            svL[g * 64 + 8 * s] = make_float4(v0, v1, v2, v3);
            #pragma unroll 1
            for (int k = 1; k < 8; ++k) {
                buildM(8 * s + k - 1, Mk);
                float t0 = v0*Mk[0] + v1*Mk[4] + v2*Mk[8]  + v3*Mk[12];
                float t1 = v0*Mk[1] + v1*Mk[5] + v2*Mk[9]  + v3*Mk[13];
                float t2 = v0*Mk[2] + v1*Mk[6] + v2*Mk[10] + v3*Mk[14];
                float t3 = v0*Mk[3] + v1*Mk[7] + v2*Mk[11] + v3*Mk[15];
                v0 = t0; v1 = t1; v2 = t2; v3 = t3;
                svL[g * 64 + 8 * s + k] = make_float4(v0, v1, v2, v3);
            }
        } else {
            // vR[n] = M[n+1..63] e0; start from T_{2s+2} at n = 8s+7
            const float* tp = sT + g * 32 + s * 4;
            float r0 = tp[0], r1 = tp[1], r2 = tp[2], r3 = tp[3];
            svR[g * 64 + 8 * s + 7] = make_float4(r0, r1, r2, r3);
            #pragma unroll 1
            for (int n = 8 * s + 6; n >= 8 * s; --n) {
                buildM(n + 1, Mk);
                float t0 = Mk[0]*r0  + Mk[1]*r1  + Mk[2]*r2  + Mk[3]*r3;
                float t1 = Mk[4]*r0  + Mk[5]*r1  + Mk[6]*r2  + Mk[7]*r3;
                float t2 = Mk[8]*r0  + Mk[9]*r1  + Mk[10]*r2 + Mk[11]*r3;
                float t3 = Mk[12]*r0 + Mk[13]*r1 + Mk[14]*r2 + Mk[15]*r3;
                r0 = t0; r1 = t1; r2 = t2; r3 = t3;
                svR[g * 64 + n] = make_float4(r0, r1, r2, r3);
            }
        }
    }
    __syncthreads();

    // ---- output phase: thread owns 1 n x 4 batches (B chunks reused 4x) ----
    {
        const int n  = tid & 63;
        const int bq = tid >> 6;           // 0..3
        const float s = sg[0];

        float u[4][4], a[4][4], H[4][4];
        #pragma unroll
        for (int b = 0; b < 4; ++b) {
            int gb = bq * 4 + b;
            float4 vl = svL[gb * 64 + n];
            float nl = sqrtf(vl.x*vl.x + vl.y*vl.y + vl.z*vl.z + vl.w*vl.w);
            float il = 1.0f / (nl + 1e-6f);
            u[b][0] = vl.x * il; u[b][1] = vl.y * il; u[b][2] = vl.z * il; u[b][3] = vl.w * il;
            float4 vr = svR[gb * 64 + n];
            float nr = sqrtf(vr.x*vr.x + vr.y*vr.y + vr.z*vr.z + vr.w*vr.w);
            float ir = 1.0f / (nr + 1e-6f);
            a[b][0] = vr.x * ir; a[b][1] = vr.y * ir; a[b][2] = vr.z * ir; a[b][3] = vr.w * ir;
            H[b][0] = 0.f; H[b][1] = 0.f; H[b][2] = 0.f; H[b][3] = 0.f;
        }

        #pragma unroll
        for (int c = 0; c < 16; ++c) {           // c = i*4 + l
            float4 bv = *(const float4*)(sB3 + (c * 64 + n) * 4);
            const int i = c >> 2, l = c & 3;
            #pragma unroll
            for (int b = 0; b < 4; ++b) {
                float w = u[b][i] * a[b][l];
                H[b][0] = fmaf(w, bv.x, H[b][0]);
                H[b][1] = fmaf(w, bv.y, H[b][1]);
                H[b][2] = fmaf(w, bv.z, H[b][2]);
                H[b][3] = fmaf(w, bv.w, H[b][3]);
            }
        }

        #pragma unroll
        for (int b = 0; b < 4; ++b) {
            int gb = bq * 4 + b;
            float f = sqrtf(H[b][0]*H[b][0] + H[b][1]*H[b][1]
                          + H[b][2]*H[b][2] + H[b][3]*H[b][3]);
            float invf = s / (f + 1e-6f);
            float h00 = fmaxf(nan0(H[b][0] * invf), 0.f);
            float h01 = fmaxf(nan0(H[b][1] * invf), 0.f);
            float h10 = fmaxf(nan0(H[b][2] * invf), 0.f);
            float h11 = fmaxf(nan0(H[b][3] * invf), 0.f);
            float2 xn = sx[gb * 65 + n];
            float y0 = fmaf(h00, xn.x, h01 * xn.y);
            float y1 = fmaf(h10, xn.x, h11 * xn.y);
            sx[gb * 65 + n] = make_float2(y0, y1);
        }
    }
    __syncthreads();

    // ---- coalesced writeback ----
    float2* yv = (float2*)yg;
    for (int idx = tid; idx < G * NN; idx += TB)
        yv[(size_t)b0 * NN + idx] = sx[(idx >> 6) * 65 + (idx & 63)];
}

extern "C" void kernel_launch(void* const* d_in, const int* in_sizes, int n_in,
                              void* d_out, int out_size) {
    const float* x = (const float*)d_in[0];
    const float* A = (const float*)d_in[1];
    const float* B = (const float*)d_in[2];
    const float* s = (const float*)d_in[3];
    float* y = (float*)d_out;

    const int batch = in_sizes[0] / (NN * 2);
    const int grid  = batch / G;
    const size_t smem = (size_t)SMEM_FLOATS * sizeof(float);

    cudaFuncSetAttribute(tdvp_kernel, cudaFuncAttributeMaxDynamicSharedMemorySize, (int)smem);
    tdvp_kernel<<<grid, TB, smem>>>(x, A, B, s, y);
}